// round 17
// baseline (speedup 1.0000x reference)
#include <cuda_runtime.h>
#include <cuda_bf16.h>
#include <cuda_fp16.h>
#include <math.h>
#include <stdint.h>

#define L_  4
#define H_  12
#define E_  768
#define HS_ 64
#define V_  32000
#define B_  2
#define T_  1024
#define BT  2048
#define FF  3072
#define NQKV 2304

// ---- weight scratch offsets (fp16 elements) ----
#define WPL 7077888ull
#define OFF_QKV(l) ((size_t)(l) * WPL)
#define OFF_O(l)   (OFF_QKV(l) + 1769472ull)
#define OFF_W1(l)  (OFF_QKV(l) + 2359296ull)
#define OFF_W2(l)  (OFF_QKV(l) + 4718592ull)
#define WTOT       ((size_t)4 * WPL)

// ---------------- scratch (static device globals) ----------------------------
__device__ float g_x[BT * E_];
__device__ __half g_qkvhi[BT * NQKV];
__device__ __half g_qkvlo[BT * NQKV];
__device__ __half g_hhi[BT * E_];
__device__ __half g_hlo[BT * E_];
__device__ __half g_ohi[BT * E_];
__device__ __half g_olo[BT * E_];
__device__ __half g_ffhi[BT * FF];
__device__ float g_bqkv[L_ * NQKV];
__device__ float g_part[2ull * BT * FF];
__device__ __half g_wth[WTOT];
__device__ __half g_wlmh[(size_t)V_ * E_];
__device__ float g_rowloss[BT];
__device__ float g_logits_scratch[(size_t)BT * V_];

// ---------------- PTX helpers ------------------------------------------------
__device__ __forceinline__ uint32_t smem_u32(const void* p) {
    uint32_t a;
    asm("{ .reg .u64 t; cvta.to.shared.u64 t, %1; cvt.u32.u64 %0, t; }" : "=r"(a) : "l"(p));
    return a;
}
__device__ __forceinline__ void mma16816h(float* c, const uint32_t* a, uint32_t b0, uint32_t b1) {
    asm volatile(
        "mma.sync.aligned.m16n8k16.row.col.f32.f16.f16.f32 "
        "{%0,%1,%2,%3}, {%4,%5,%6,%7}, {%8,%9}, {%0,%1,%2,%3};"
        : "+f"(c[0]), "+f"(c[1]), "+f"(c[2]), "+f"(c[3])
        : "r"(a[0]), "r"(a[1]), "r"(a[2]), "r"(a[3]), "r"(b0), "r"(b1));
}
__device__ __forceinline__ void ldsm4(uint32_t* r, uint32_t addr) {
    asm volatile("ldmatrix.sync.aligned.m8n8.x4.shared.b16 {%0,%1,%2,%3}, [%4];"
                 : "=r"(r[0]), "=r"(r[1]), "=r"(r[2]), "=r"(r[3]) : "r"(addr));
}
__device__ __forceinline__ void cpasync16(uint32_t dst, const void* src) {
    asm volatile("cp.async.cg.shared.global [%0], [%1], 16;" :: "r"(dst), "l"(src));
}

// ---------------- fused QKV weight repack+transpose -> fp16 + bias concat ----
__global__ __launch_bounds__(256) void wconv_qkv_kernel(const float* __restrict__ Wq,
                                                        const float* __restrict__ Wk,
                                                        const float* __restrict__ Wv,
                                                        const float* __restrict__ bq,
                                                        const float* __restrict__ bk,
                                                        const float* __restrict__ bv,
                                                        __half* __restrict__ Wt,
                                                        float* __restrict__ bqkv,
                                                        int l) {
    __shared__ float s[32][33];
    int n0 = blockIdx.y * 32, e0 = blockIdx.x * 32;
    int tx = threadIdx.x, ty = threadIdx.y;
    int sel = n0 / E_;
    int nn = n0 % E_;
    int h = nn >> 6, hs0 = nn & 63;
    const float* src = sel == 0 ? Wq : (sel == 1 ? Wk : Wv);
    const float* base = src + ((size_t)(l * H_ + h) * E_) * 64;
#pragma unroll
    for (int i = 0; i < 4; i++) {
        int e = ty + 8 * i;
        s[e][tx] = base[(size_t)(e0 + e) * 64 + hs0 + tx];
    }
    __syncthreads();
#pragma unroll
    for (int i = 0; i < 4; i++) {
        int nl = ty + 8 * i;
        Wt[(size_t)(n0 + nl) * E_ + e0 + tx] = __float2half_rn(s[tx][nl]);
    }
    int gid = (blockIdx.y * gridDim.x + blockIdx.x) * 256 + ty * 32 + tx;
    if (gid < NQKV) {
        float v;
        if (gid < E_)            v = bq[l * E_ + gid];
        else if (gid < 2 * E_)   v = bk[l * E_ + gid - E_];
        else                     v = bv[l * E_ + gid - 2 * E_];
        bqkv[l * NQKV + gid] = v;
    }
}

// ---------------- generic weight transpose -> single fp16 --------------------
__global__ __launch_bounds__(256) void wconvt_h_kernel(const float* __restrict__ W,
                                                       __half* __restrict__ Wt,
                                                       int K, int N) {
    __shared__ float s[32][33];
    int k0 = blockIdx.y * 32, n0 = blockIdx.x * 32;
    int tx = threadIdx.x, ty = threadIdx.y;
#pragma unroll
    for (int i = 0; i < 4; i++)
        s[ty + 8 * i][tx] = W[(size_t)(k0 + ty + 8 * i) * N + n0 + tx];
    __syncthreads();
#pragma unroll
    for (int i = 0; i < 4; i++) {
        int n = ty + 8 * i;
        Wt[(size_t)(n0 + n) * K + k0 + tx] = __float2half_rn(s[tx][n]);
    }
}

// ---------------- fused embedding + layernorm -> fp16 hi/lo -------------------
__global__ __launch_bounds__(256) void embed_ln_kernel(const int* __restrict__ idx,
                                                       const float* __restrict__ tok,
                                                       const float* __restrict__ pos,
                                                       const float* __restrict__ g,
                                                       const float* __restrict__ b,
                                                       float* __restrict__ x,
                                                       __half* __restrict__ hi,
                                                       __half* __restrict__ lo) {
    int row = blockIdx.x;
    int tid = threadIdx.x;
    int token = idx[row];
    int tp = row % T_;
    size_t rb = (size_t)row * E_;
    float v[3], s = 0.f, sq = 0.f;
#pragma unroll
    for (int i = 0; i < 3; i++) {
        int e = tid + (i << 8);
        float t = tok[(size_t)token * E_ + e] + pos[(size_t)tp * E_ + e];
        x[rb + e] = t;
        v[i] = t; s += t; sq += t * t;
    }
#pragma unroll
    for (int o = 16; o > 0; o >>= 1) {
        s  += __shfl_xor_sync(0xffffffffu, s, o);
        sq += __shfl_xor_sync(0xffffffffu, sq, o);
    }
    __shared__ float ss[8], ssq[8];
    if ((tid & 31) == 0) { ss[tid >> 5] = s; ssq[tid >> 5] = sq; }
    __syncthreads();
    s = 0.f; sq = 0.f;
#pragma unroll
    for (int i = 0; i < 8; i++) { s += ss[i]; sq += ssq[i]; }
    float mean = s * (1.f / E_);
    float var  = sq * (1.f / E_) - mean * mean;
    float rstd = rsqrtf(var + 1e-5f);
#pragma unroll
    for (int i = 0; i < 3; i++) {
        int e = tid + (i << 8);
        float y = (v[i] - mean) * rstd * g[e] + b[e];
        __half h = __float2half_rn(y);
        hi[rb + e] = h;
        lo[rb + e] = __float2half_rn(y - __half2float(h));
    }
}

// ---------------- fused split-K reduce + residual + layernorm ----------------
template<int WRITE_LO>
__global__ __launch_bounds__(256) void reduce_ln_kernel(const float* __restrict__ parts,
                                                        int nsplit,
                                                        const float* __restrict__ bias,
                                                        float* __restrict__ x,
                                                        const float* __restrict__ g,
                                                        const float* __restrict__ b,
                                                        __half* __restrict__ hi,
                                                        __half* __restrict__ lo) {
    int row = blockIdx.x, tid = threadIdx.x;
    size_t rb = (size_t)row * E_;
    const size_t plane = (size_t)BT * E_;
    float v[3], s = 0.f, sq = 0.f;
#pragma unroll
    for (int i = 0; i < 3; i++) {
        int e = tid + (i << 8);
        size_t ix = rb + e;
        float t = parts[ix];
        for (int p = 1; p < nsplit; p++) t += parts[plane * p + ix];
        t += bias[e] + x[ix];
        x[ix] = t;
        v[i] = t; s += t; sq += t * t;
    }
#pragma unroll
    for (int o = 16; o > 0; o >>= 1) {
        s  += __shfl_xor_sync(0xffffffffu, s, o);
        sq += __shfl_xor_sync(0xffffffffu, sq, o);
    }
    __shared__ float ss[8], ssq[8];
    if ((tid & 31) == 0) { ss[tid >> 5] = s; ssq[tid >> 5] = sq; }
    __syncthreads();
    s = 0.f; sq = 0.f;
#pragma unroll
    for (int i = 0; i < 8; i++) { s += ss[i]; sq += ssq[i]; }
    float mean = s * (1.f / E_);
    float var  = sq * (1.f / E_) - mean * mean;
    float rstd = rsqrtf(var + 1e-5f);
#pragma unroll
    for (int i = 0; i < 3; i++) {
        int e = tid + (i << 8);
        float y = (v[i] - mean) * rstd * g[e] + b[e];
        __half h = __float2half_rn(y);
        hi[rb + e] = h;
        if (WRITE_LO)
            lo[rb + e] = __float2half_rn(y - __half2float(h));
    }
}

// ---------------- fp16 tensor-core GEMM (narrow: 128x128, 1/2 sweeps) --------
#define LSTG 24576
#define GEMM_H_SMEM (4 * LSTG)
__global__ __launch_bounds__(256, 2)
void gemm_h_kernel(const __half* __restrict__ Ahi,
                   const __half* __restrict__ Alo,
                   const __half* __restrict__ Bt,
                   const float* __restrict__ bias,
                   float* __restrict__ C,
                   __half* __restrict__ Chi,
                   __half* __restrict__ Clo,
                   float* __restrict__ Cpart,
                   int N, int K, int kslen, int nsweep, int relu) {
    extern __shared__ __align__(16) char smem[];
    int tid = threadIdx.x, lane = tid & 31, wid = tid >> 5;
    int wm = wid >> 2, wn = wid & 3;
    int row0 = blockIdx.y << 7, col0 = blockIdx.x << 7;
    int k0base = blockIdx.z * kslen;
    uint32_t sb = smem_u32(smem);

    float acc[4][4][4] = {};
    const int nCh = kslen >> 5;
    int frow = tid >> 1;
    int fc0 = (tid & 1) << 1;
    uint32_t fsw = (uint32_t)((frow >> 1) & 3);

    auto loadStage = [&](int stg, int c) {
        if (c < nCh) {
            uint32_t st = sb + stg * LSTG;
            int k0 = k0base + (c << 5);
            size_t abase = (size_t)(row0 + frow) * K + k0;
            size_t bbase = (size_t)(col0 + frow) * K + k0;
#pragma unroll
            for (int cc = 0; cc < 2; cc++) {
                int cl = fc0 + cc;
                uint32_t doff = (uint32_t)(frow << 6) + (((uint32_t)cl ^ fsw) << 4);
                cpasync16(st + doff,         Ahi + abase + (cl << 3));
                if (nsweep > 1)
                    cpasync16(st + 8192 + doff, Alo + abase + (cl << 3));
                cpasync16(st + 16384 + doff, Bt + bbase + (cl << 3));
            }
        }
        asm volatile("cp.async.commit_group;" ::: "memory");
    };

    int arow[4], brow[2];
    uint32_t asw[4], bsw[2];
#pragma unroll
    for (int mf = 0; mf < 4; mf++) {
        arow[mf] = (wm << 6) + (mf << 4) + (lane & 15);
        asw[mf] = (uint32_t)((arow[mf] >> 1) & 3);
    }
#pragma unroll
    for (int g = 0; g < 2; g++) {
        brow[g] = (wn << 5) + (g << 4) + (lane & 7) + (((lane >> 3) & 1) << 3);
        bsw[g] = (uint32_t)((brow[g] >> 1) & 3);
    }
    int kc = lane >> 4;

    loadStage(0, 0);
    loadStage(1, 1);
    loadStage(2, 2);

    int stg = 0;
    for (int c = 0; c < nCh; ++c) {
        asm volatile("cp.async.wait_group 2;" ::: "memory");
        __syncthreads();
        loadStage((stg + 3) & 3, c + 3);
        uint32_t st = sb + stg * LSTG;
#pragma unroll
        for (int ks = 0; ks < 2; ks++) {
            int cl = (ks << 1) + kc;
            uint32_t ah[4][4], bb[2][4];
#pragma unroll
            for (int mf = 0; mf < 4; mf++)
                ldsm4(ah[mf], st + (uint32_t)(arow[mf] << 6) + (((uint32_t)cl ^ asw[mf]) << 4));
#pragma unroll
            for (int g = 0; g < 2; g++)
                ldsm4(bb[g], st + 16384 + (uint32_t)(brow[g] << 6) + (((uint32_t)cl ^ bsw[g]) << 4));
#pragma unroll
            for (int mf = 0; mf < 4; mf++)
#pragma unroll
                for (int nf = 0; nf < 4; nf++)
                    mma16816h(acc[mf][nf], ah[mf], bb[nf >> 1][nf & 1], bb[nf >> 1][(nf & 1) + 2]);
            if (nsweep > 1) {
                uint32_t al[4][4];
#pragma unroll
                for (int mf = 0; mf < 4; mf++)
                    ldsm4(al[mf], st + 8192 + (uint32_t)(arow[mf] << 6) + (((uint32_t)cl ^ asw[mf]) << 4));
#pragma unroll
                for (int mf = 0; mf < 4; mf++)
#pragma unroll
                    for (int nf = 0; nf < 4; nf++)
                        mma16816h(acc[mf][nf], al[mf], bb[nf >> 1][nf & 1], bb[nf >> 1][(nf & 1) + 2]);
            }
        }
        stg = (stg + 1) & 3;
    }

    if (Cpart) {
        size_t plane = (size_t)blockIdx.z * (((size_t)gridDim.y << 7) * (size_t)N);
#pragma unroll
        for (int mf = 0; mf < 4; mf++) {
            int rbase = row0 + (wm << 6) + (mf << 4) + (lane >> 2);
#pragma unroll
            for (int nf = 0; nf < 4; nf++) {
                int cb = col0 + (wn << 5) + (nf << 3) + ((lane & 3) << 1);
#pragma unroll
                for (int half = 0; half < 2; half++) {
                    int r = rbase + (half << 3);
                    *(float2*)(Cpart + plane + (size_t)r * N + cb) =
                        make_float2(acc[mf][nf][half * 2], acc[mf][nf][half * 2 + 1]);
                }
            }
        }
        return;
    }
#pragma unroll
    for (int mf = 0; mf < 4; mf++) {
        int rbase = row0 + (wm << 6) + (mf << 4) + (lane >> 2);
#pragma unroll
        for (int nf = 0; nf < 4; nf++) {
            int cb = col0 + (wn << 5) + (nf << 3) + ((lane & 3) << 1);
            float b0 = bias ? bias[cb] : 0.f;
            float b1 = bias ? bias[cb + 1] : 0.f;
#pragma unroll
            for (int half = 0; half < 2; half++) {
                int r = rbase + (half << 3);
                float v0 = acc[mf][nf][half * 2 + 0] + b0;
                float v1 = acc[mf][nf][half * 2 + 1] + b1;
                if (relu) { v0 = fmaxf(v0, 0.f); v1 = fmaxf(v1, 0.f); }
                size_t gi = (size_t)r * N + cb;
                if (Chi) {
                    __half2 h = __floats2half2_rn(v0, v1);
                    *(__half2*)(Chi + gi) = h;
                    if (Clo) {
                        float2 hf = __half22float2(h);
                        __half2 l = __floats2half2_rn(v0 - hf.x, v1 - hf.y);
                        *(__half2*)(Clo + gi) = l;
                    }
                } else {
                    *(float2*)(C + gi) = make_float2(v0, v1);
                }
            }
        }
    }
}

// ---------------- fp16 wide GEMM (128x256 tile, 1-sweep, 4 stages) -----------
// warp tile 64x64; acc 128 regs; 1 CTA/SM. Stage 24KB: A@0 (8K), B@8192 (16K).
#define WSTG 24576
#define GEMM_HW_SMEM (4 * WSTG)
__global__ __launch_bounds__(256, 1)
void gemm_hw_kernel(const __half* __restrict__ Ahi,
                    const __half* __restrict__ Bt,
                    const float* __restrict__ bias,
                    float* __restrict__ C,
                    __half* __restrict__ Chi,
                    int N, int K, int relu) {
    extern __shared__ __align__(16) char smem[];
    int tid = threadIdx.x, lane = tid & 31, wid = tid >> 5;
    int wm = wid >> 2, wn = wid & 3;
    int row0 = blockIdx.y << 7, col0 = blockIdx.x << 8;
    uint32_t sb = smem_u32(smem);

    float acc[4][8][4] = {};
    const int nCh = K >> 5;
    int frow = tid >> 1;
    int fc0 = (tid & 1) << 1;
    uint32_t fsw = (uint32_t)((frow >> 1) & 3);
    uint32_t bfsw = (uint32_t)((tid >> 1) & 3);

    auto loadStage = [&](int stg, int c) {
        if (c < nCh) {
            uint32_t st = sb + stg * WSTG;
            int k0 = c << 5;
            size_t abase = (size_t)(row0 + frow) * K + k0;
#pragma unroll
            for (int cc = 0; cc < 2; cc++) {
                int cl = fc0 + cc;
                uint32_t doff = (uint32_t)(frow << 6) + (((uint32_t)cl ^ fsw) << 4);
                cpasync16(st + doff, Ahi + abase + (cl << 3));
            }
            size_t bbase = (size_t)(col0 + tid) * K + k0;
#pragma unroll
            for (int cl = 0; cl < 4; cl++) {
                uint32_t doff = (uint32_t)(tid << 6) + (((uint32_t)cl ^ bfsw) << 4);
                cpasync16(st + 8192 + doff, Bt + bbase + (cl << 3));
            }
        }
        asm volatile("cp.async.commit_group;" ::: "memory");
    };

    int arow[4], brow[4];
    uint32_t asw[4], bsw[4];
#pragma unroll
    for (int mf = 0; mf < 4; mf++) {
        arow[mf] = (wm << 6) + (mf << 4) + (lane & 15);
        asw[mf] = (uint32_t)((arow[mf] >> 1) & 3);
    }
#pragma unroll
    for (int g = 0; g < 4; g++) {
        brow[g] = (wn << 6) + (g << 4) + (lane & 7) + (((lane >> 3) & 1) << 3);
        bsw[g] = (uint32_t)((brow[g] >> 1) & 3);
    }
    int kc = lane >> 4;

    loadStage(0, 0);
    loadStage(1, 1);
    loadStage(2, 2);

    int stg = 0;
    for (int c = 0; c < nCh; ++c) {
        asm volatile("cp.async.wait_group 2;" ::: "memory");
        __syncthreads();
        loadStage((stg + 3) & 3, c + 3);
        uint32_t st = sb + stg * WSTG;
#pragma unroll
        for (int ks = 0; ks < 2; ks++) {
            int cl = (ks << 1) + kc;
            uint32_t ah[4][4], bb[4][4];
#pragma unroll
            for (int mf = 0; mf < 4; mf++)
                ldsm4(ah[mf], st + (uint32_t)(arow[mf] << 6) + (((uint32_t)cl ^ asw[mf]) << 4));
#pragma unroll
            for (int g = 0; g < 4; g++)
                ldsm4(bb[g], st + 8192 + (uint32_t)(brow[g] << 6) + (((uint32_t)cl ^ bsw[g]) << 4));
#pragma unroll
            for (int mf = 0; mf < 4; mf++)
#pragma unroll
                for (int nf = 0; nf < 8; nf++)
                    mma16816h(acc[mf][nf], ah[mf], bb[nf >> 1][nf & 1], bb[nf >> 1][(nf & 1) + 2]);
        }
        stg = (stg + 1) & 3;
    }

#pragma unroll
    for (int mf = 0; mf < 4; mf++) {
        int rbase = row0 + (wm << 6) + (mf << 4) + (lane >> 2);
#pragma unroll
        for (int nf = 0; nf < 8; nf++) {
            int cb = col0 + (wn << 6) + (nf << 3) + ((lane & 3) << 1);
            float b0 = bias ? bias[cb] : 0.f;
            float b1 = bias ? bias[cb + 1] : 0.f;
#pragma unroll
            for (int half = 0; half < 2; half++) {
                int r = rbase + (half << 3);
                float v0 = acc[mf][nf][half * 2 + 0] + b0;
                float v1 = acc[mf][nf][half * 2 + 1] + b1;
                if (relu) { v0 = fmaxf(v0, 0.f); v1 = fmaxf(v1, 0.f); }
                size_t gi = (size_t)r * N + cb;
                if (Chi) {
                    *(__half2*)(Chi + gi) = __floats2half2_rn(v0, v1);
                } else {
                    *(float2*)(C + gi) = make_float2(v0, v1);
                }
            }
        }
    }
}

// ---------------- tensor-core flash attention (fp16 2-sweep, K/V dbl-buf) ----
#define ATT_SMEM 57344
__global__ __launch_bounds__(128)
void attn_kernel(const __half* __restrict__ qkvhi,
                 const __half* __restrict__ qkvlo,
                 __half* __restrict__ ohi,
                 __half* __restrict__ olo) {
    extern __shared__ __align__(16) char smem[];
    uint32_t sb = smem_u32(smem);
    const uint32_t Q_HI = 0, Q_LO = 8192, K_HI = 16384, VS_HI = 32768, VT_HI = 49152;
    int tid = threadIdx.x, lane = tid & 31, w = tid >> 5;
    int qt = (int)gridDim.x - 1 - (int)blockIdx.x;
    int bh = blockIdx.y;
    int bb = bh / H_, hh = bh % H_;
    size_t qrowbase = (size_t)(bb * T_ + (qt << 6));
    const int coff = hh * 64;
    int kc = lane >> 4;

    {
        int r0 = tid >> 1;
        int c0 = (tid & 1) << 2;
        size_t g = (qrowbase + r0) * (size_t)NQKV + coff;
#pragma unroll
        for (int i = 0; i < 4; i++) {
            int c = c0 + i;
            uint32_t d = (uint32_t)(r0 << 7) + (((uint32_t)(c ^ (r0 & 7))) << 4);
            cpasync16(sb + Q_HI + d, qkvhi + g + (c << 3));
            cpasync16(sb + Q_LO + d, qkvlo + g + (c << 3));
        }
        asm volatile("cp.async.commit_group;\n\tcp.async.wait_group 0;" ::: "memory");
    }
    __syncthreads();
    uint32_t qh[4][4], ql[4][4];
    {
        int aRow = (w << 4) + (lane & 15);
#pragma unroll
        for (int ks = 0; ks < 4; ks++) {
            int cl = (ks << 1) + kc;
            uint32_t ad = (uint32_t)(aRow << 7) + (((uint32_t)(cl ^ (aRow & 7))) << 4);
            ldsm4(qh[ks], sb + Q_HI + ad);
            ldsm4(ql[ks], sb + Q_LO + ad);
        }
    }

    auto loadKV = [&](int kt2, int buf) {
        if (kt2 <= qt) {
            int r0 = tid >> 1;
            int c0 = (tid & 1) << 2;
            size_t kb = (size_t)(bb * T_ + (kt2 << 6));
            size_t gk = (kb + r0) * (size_t)NQKV + E_ + coff;
            size_t gv = (kb + r0) * (size_t)NQKV + 2 * E_ + coff;
            uint32_t boff = (uint32_t)buf << 13;
#pragma unroll
            for (int i = 0; i < 4; i++) {
                int c = c0 + i;
                uint32_t d = (uint32_t)(r0 << 7) + (((uint32_t)(c ^ (r0 & 7))) << 4);
                cpasync16(sb + K_HI + boff + d,  qkvhi + gk + (c << 3));
                cpasync16(sb + VS_HI + boff + d, qkvhi + gv + (c << 3));
            }
        }
        asm volatile("cp.async.commit_group;" ::: "memory");
    };

    float oacc[8][4] = {};
    float m1 = -INFINITY, m2 = -INFINITY, l1 = 0.f, l2 = 0.f;
    int r1 = lane >> 2;
    int rowg1 = (qt << 6) + (w << 4) + r1;
    int rowg2 = rowg1 + 8;

    loadKV(0, 0);

    for (int kt = 0; kt <= qt; kt++) {
        int buf = kt & 1;
        uint32_t boff = (uint32_t)buf << 13;
        asm volatile("cp.async.wait_group 0;" ::: "memory");
        __syncthreads();
        loadKV(kt + 1, buf ^ 1);

        {
            int kvp = tid & 31;
            int dg0 = tid >> 5;
            int kv = kvp << 1;
#pragma unroll
            for (int t = 0; t < 2; t++) {
                int ch = dg0 + (t << 2);
                int d0 = ch << 3;
                uint32_t a0 = (uint32_t)(kv << 7) + (((uint32_t)ch ^ (uint32_t)(kv & 7)) << 4);
                uint32_t a1 = (uint32_t)((kv + 1) << 7) + (((uint32_t)ch ^ (uint32_t)((kv + 1) & 7)) << 4);
                uint4 h0 = *(const uint4*)(smem + VS_HI + boff + a0);
                uint4 h1 = *(const uint4*)(smem + VS_HI + boff + a1);
                const __half* ph0 = (const __half*)&h0;
                const __half* ph1 = (const __half*)&h1;
#pragma unroll
                for (int j = 0; j < 8; j++) {
                    int d = d0 + j;
                    uint32_t ad = (uint32_t)(d << 7) +
                                  ((((uint32_t)(kvp >> 2) ^ (uint32_t)(d & 7)) << 4)) +
                                  ((uint32_t)(kvp & 3) << 2);
                    __half2 hw; hw.x = ph0[j]; hw.y = ph1[j];
                    *(__half2*)(smem + VT_HI + ad) = hw;
                }
            }
        }
        __syncthreads();

        float sacc[8][4] = {};
#pragma unroll
        for (int ks = 0; ks < 4; ks++) {
            int cl = (ks << 1) + kc;
            uint32_t kh[4][4];
#pragma unroll
            for (int g = 0; g < 4; g++) {
                int bRow = (g << 4) + (lane & 7) + (((lane >> 3) & 1) << 3);
                uint32_t bd = (uint32_t)(bRow << 7) + (((uint32_t)(cl ^ (bRow & 7))) << 4);
                ldsm4(kh[g], sb + K_HI + boff + bd);
            }
#pragma unroll
            for (int g = 0; g < 4; g++)
#pragma unroll
                for (int nfp = 0; nfp < 2; nfp++)
                    mma16816h(sacc[2 * g + nfp], qh[ks], kh[g][nfp], kh[g][nfp + 2]);
#pragma unroll
            for (int g = 0; g < 4; g++)
#pragma unroll
                for (int nfp = 0; nfp < 2; nfp++)
                    mma16816h(sacc[2 * g + nfp], ql[ks], kh[g][nfp], kh[g][nfp + 2]);
        }
#pragma unroll
        for (int nf = 0; nf < 8; nf++) {
            sacc[nf][0] *= 0.125f; sacc[nf][1] *= 0.125f;
            sacc[nf][2] *= 0.125f; sacc[nf][3] *= 0.125f;
        }
        if (kt == qt) {
#pragma unroll
            for (int nf = 0; nf < 8; nf++) {
                int colb = (kt << 6) + (nf << 3) + ((lane & 3) << 1);
                if (colb > rowg1)     sacc[nf][0] = -INFINITY;
                if (colb + 1 > rowg1) sacc[nf][1] = -INFINITY;
                if (colb > rowg2)     sacc[nf][2] = -INFINITY;
                if (colb + 1 > rowg2) sacc[nf][3] = -INFINITY;
            }
        }
        float t1 = -INFINITY, t2 = -INFINITY;
#pragma unroll
        for (int nf = 0; nf < 8; nf++) {
            t1 = fmaxf(t1, fmaxf(sacc[nf][0], sacc[nf][1]));
            t2 = fmaxf(t2, fmaxf(sacc[nf][2], sacc[nf][3]));
        }
        t1 = fmaxf(t1, __shfl_xor_sync(0xffffffffu, t1, 1));
        t1 = fmaxf(t1, __shfl_xor_sync(0xffffffffu, t1, 2));
        t2 = fmaxf(t2, __shfl_xor_sync(0xffffffffu, t2, 1));
        t2 = fmaxf(t2, __shfl_xor_sync(0xffffffffu, t2, 2));
        float mn1 = fmaxf(m1, t1), mn2 = fmaxf(m2, t2);
        float a1 = __expf(m1 - mn1), a2 = __expf(m2 - mn2);
        float ps1 = 0.f, ps2 = 0.f;
#pragma unroll
        for (int nf = 0; nf < 8; nf++) {
            sacc[nf][0] = __expf(sacc[nf][0] - mn1);
            sacc[nf][1] = __expf(sacc[nf][1] - mn1);
            sacc[nf][2] = __expf(sacc[nf][2] - mn2);
            sacc[nf][3] = __expf(sacc[nf][3] - mn2);
            ps1 += sacc[nf][0] + sacc[nf][1];
            ps2 += sacc[nf][2] + sacc[nf][3];
        }
        ps1 += __shfl_xor_sync(0xffffffffu, ps1, 1);
        ps1 += __shfl_xor_sync(0xffffffffu, ps1, 2);
        ps2 += __shfl_xor_sync(0xffffffffu, ps2, 1);
        ps2 += __shfl_xor_sync(0xffffffffu, ps2, 2);
        l1 = l1 * a1 + ps1;
        l2 = l2 * a2 + ps2;
        m1 = mn1; m2 = mn2;
#pragma unroll
        for (int nf = 0; nf < 8; nf++) {
            oacc[nf][0] *= a1; oacc[nf][1] *= a1;
            oacc[nf][2] *= a2; oacc[nf][3] *= a2;
        }
#pragma unroll
        for (int j = 0; j < 4; j++) {
            uint32_t pah[4], pal[4];
#pragma unroll
            for (int half = 0; half < 2; half++) {
                float x0 = sacc[2 * j + half][0], x1 = sacc[2 * j + half][1];
                float x2 = sacc[2 * j + half][2], x3 = sacc[2 * j + half][3];
                __half2 h01 = __floats2half2_rn(x0, x1);
                __half2 h23 = __floats2half2_rn(x2, x3);
                float2 f01 = __half22float2(h01), f23 = __half22float2(h23);
                __half2 lo01 = __floats2half2_rn(x0 - f01.x, x1 - f01.y);
                __half2 lo23 = __floats2half2_rn(x2 - f23.x, x3 - f23.y);
                pah[2 * half + 0] = *(uint32_t*)&h01;
                pah[2 * half + 1] = *(uint32_t*)&h23;
                pal[2 * half + 0] = *(uint32_t*)&lo01;
                pal[2 * half + 1] = *(uint32_t*)&lo23;
            }
            int cl = (j << 1) + kc;
            uint32_t vh[4][4];
#pragma unroll
            for (int g = 0; g < 4; g++) {
                int bRow = (g << 4) + (lane & 7) + (((lane >> 3) & 1) << 3);
                uint32_t bd = (uint32_t)(bRow << 7) + (((uint32_t)(cl ^ (bRow & 7))) << 4);
                ldsm4(vh[g], sb + VT_HI + bd);
            }
#pragma unroll
            for (int g = 0; g < 4; g++)
#pragma unroll
                for (int nfp = 0; nfp < 2; nfp++)
                    mma16816h(oacc[2 * g + nfp], pah, vh[g][nfp], vh[g][nfp + 2]);
#pragma unroll
            for (int g = 0; g < 4; g++)
#pragma unroll
                for (int nfp = 0; nfp < 2; nfp++)
                    mma16816h(oacc[2 * g + nfp], pal, vh[g][nfp], vh[g][nfp + 2]);
        }
    }

    float li1 = 1.f / l1, li2 = 1.f / l2;
    size_t ob1 = (qrowbase + (w << 4) + r1) * (size_t)E_ + coff;
    size_t ob2 = ob1 + (size_t)8 * E_;
#pragma unroll
    for (int nf = 0; nf < 8; nf++) {
        int d = (nf << 3) + ((lane & 3) << 1);
        float v0 = oacc[nf][0] * li1, v1 = oacc[nf][1] * li1;
        __half2 h = __floats2half2_rn(v0, v1);
        float2 hf = __half22float2(h);
        __half2 lo = __floats2half2_rn(v0 - hf.x, v1 - hf.y);
        *(__half2*)(ohi + ob1 + d) = h;
        *(__half2*)(olo + ob1 + d) = lo;
        float v2 = oacc[nf][2] * li2, v3 = oacc[nf][3] * li2;
        __half2 h2 = __floats2half2_rn(v2, v3);
        float2 hf2 = __half22float2(h2);
        __half2 lo2 = __floats2half2_rn(v2 - hf2.x, v3 - hf2.y);
        *(__half2*)(ohi + ob2 + d) = h2;
        *(__half2*)(olo + ob2 + d) = lo2;
    }
}

// ---------------- loss ------------------------------------------------------
__global__ __launch_bounds__(256) void row_lse_kernel(const float* __restrict__ logits,
                                                      const int* __restrict__ targets,
                                                      float* __restrict__ rowloss) {
    int row = blockIdx.x, tid = threadIdx.x;
    const float* lr = logits + (size_t)row * V_;
    float mx = -INFINITY;
    for (int i = tid; i < V_; i += 256) mx = fmaxf(mx, lr[i]);
#pragma unroll
    for (int o = 16; o > 0; o >>= 1) mx = fmaxf(mx, __shfl_xor_sync(0xffffffffu, mx, o));
    __shared__ float sm[8];
    if ((tid & 31) == 0) sm[tid >> 5] = mx;
    __syncthreads();
    float m2 = -INFINITY;
#pragma unroll
    for (int i = 0; i < 8; i++) m2 = fmaxf(m2, sm[i]);
    float se = 0.f;
    for (int i = tid; i < V_; i += 256) se += __expf(lr[i] - m2);
#pragma unroll
    for (int o = 16; o > 0; o >>= 1) se += __shfl_xor_sync(0xffffffffu, se, o);
    __shared__ float ssum[8];
    if ((tid & 31) == 0) ssum[tid >> 5] = se;
    __syncthreads();
    if (tid == 0) {
        float tot = 0.f;
#pragma unroll
        for (int i = 0; i < 8; i++) tot += ssum[i];
        rowloss[row] = (logf(tot) + m2) - lr[targets[row]];
    }
}

__global__ __launch_bounds__(256) void loss_reduce_kernel(const float* __restrict__ rowloss,
                                                          float* __restrict__ out) {
    int tid = threadIdx.x;
    float s = 0.f;
    for (int i = tid; i < BT; i += 256) s += rowloss[i];
#pragma unroll
    for (int o = 16; o > 0; o >>= 1) s += __shfl_xor_sync(0xffffffffu, s, o);
    __shared__ float sm[8];
    if ((tid & 31) == 0) sm[tid >> 5] = s;
    __syncthreads();
    if (tid == 0) {
        float t = 0.f;
#pragma unroll
        for (int i = 0; i < 8; i++) t += sm[i];
        out[0] = t * (1.f / BT);
    }
}

// ---------------- launch ----------------------------------------------------
extern "C" void kernel_launch(void* const* d_in, const int* in_sizes, int n_in,
                              void* d_out, int out_size) {
    const int*   idx     = (const int*)d_in[0];
    const int*   targets = (const int*)d_in[1];
    const float* tok_emb = (const float*)d_in[2];
    const float* pos_emb = (const float*)d_in[3];
    const float* Wq  = (const float*)d_in[4];
    const float* bq  = (const float*)d_in[5];
    const float* Wk  = (const float*)d_in[6];
    const float* bk  = (const float*)d_in[7];
    const float* Wv  = (const float*)d_in[8];
    const float* bv  = (const float*)d_in[9];
    const float* Wo  = (const float*)d_in[10];
    const float* bo  = (const float*)d_in[11];
    const float* ln1g = (const float*)d_in[12];
    const float* ln1b = (const float*)d_in[13];
    const float* W1  = (const float*)d_in[14];
    const float* b1  = (const float*)d_in[15];
    const float* W2  = (const float*)d_in[16];
    const float* b2  = (const float*)d_in[17];
    const float* ln2g = (const float*)d_in[18];
    const float* ln2b = (const float*)d_in[19];
    const float* lnfg = (const float*)d_in[20];
    const float* lnfb = (const float*)d_in[21];
    const float* Wlm = (const float*)d_in[22];
    const float* blm = (const float*)d_in[23];
    float* out = (float*)d_out;

    float *px, *pbqkv, *ppart, *prl, *plg;
    __half *pqkvhi, *pqkvlo, *phhi, *phlo, *pohi, *polo, *pffhi, *pwth, *pwlmh;
    cudaGetSymbolAddress((void**)&px,     g_x);
    cudaGetSymbolAddress((void**)&pqkvhi, g_qkvhi);
    cudaGetSymbolAddress((void**)&pqkvlo, g_qkvlo);
    cudaGetSymbolAddress((void**)&phhi,   g_hhi);
    cudaGetSymbolAddress((void**)&phlo,   g_hlo);
    cudaGetSymbolAddress((void**)&pohi,   g_ohi);
    cudaGetSymbolAddress((void**)&polo,   g_olo);
    cudaGetSymbolAddress((void**)&pffhi,  g_ffhi);
    cudaGetSymbolAddress((void**)&pbqkv,  g_bqkv);
    cudaGetSymbolAddress((void**)&ppart,  g_part);
    cudaGetSymbolAddress((void**)&pwth,   g_wth);
    cudaGetSymbolAddress((void**)&pwlmh,  g_wlmh);
    cudaGetSymbolAddress((void**)&prl,    g_rowloss);
    cudaGetSymbolAddress((void**)&plg,    g_logits_scratch);

    cudaFuncSetAttribute(gemm_h_kernel,  cudaFuncAttributeMaxDynamicSharedMemorySize, GEMM_H_SMEM);
    cudaFuncSetAttribute(gemm_hw_kernel, cudaFuncAttributeMaxDynamicSharedMemorySize, GEMM_HW_SMEM);
    cudaFuncSetAttribute(attn_kernel,    cudaFuncAttributeMaxDynamicSharedMemorySize, ATT_SMEM);

    const long long NLOG = (long long)BT * V_;
    float* logits = (out_size >= NLOG) ? out : plg;

    dim3 cb(32, 8);
    dim3 gQKVw(E_ / 32, NQKV / 32);
    dim3 gQKV(NQKV / 128, BT / 128);
    dim3 gWo(E_ / 128, BT / 128, 3);
    dim3 gW1(FF / 256, BT / 128);        // wide tile
    dim3 gW2(E_ / 128, BT / 128, 3);
    dim3 gVd(V_ / 256, BT / 128);        // wide tile
    dim3 gAttn(T_ / 64, B_ * H_);

    for (int l = 0; l < L_; l++) {
        if (l == 0)
            embed_ln_kernel<<<BT, 256>>>(idx, tok_emb, pos_emb, ln1g, ln1b, px, phhi, phlo); // 0
        wconv_qkv_kernel<<<gQKVw, cb>>>(Wq, Wk, Wv, bq, bk, bv,
                                        pwth + OFF_QKV(l), pbqkv, l);                        // 1
        gemm_h_kernel<<<gQKV, 256, GEMM_H_SMEM>>>(phhi, phlo, pwth + OFF_QKV(l),             // 2
            pbqkv + l * NQKV, nullptr, pqkvhi, pqkvlo, nullptr, NQKV, E_, E_, 2, 0);
        attn_kernel<<<gAttn, 128, ATT_SMEM>>>(pqkvhi, pqkvlo, pohi, polo);                   // 3 (= global 5)
        wconvt_h_kernel<<<dim3(E_ / 32, E_ / 32), cb>>>(Wo + (size_t)l * E_ * E_,
            pwth + OFF_O(l), E_, E_);
        gemm_h_kernel<<<gWo, 256, GEMM_H_SMEM>>>(pohi, polo, pwth + OFF_O(l),
            nullptr, nullptr, nullptr, nullptr, ppart, E_, E_, 256, 2, 0);
        reduce_ln_kernel<0><<<BT, 256>>>(ppart, 3, bo + l * E_, px,
                                         ln2g + l * E_, ln2b + l * E_, phhi, nullptr);
        wconvt_h_kernel<<<dim3(FF / 32, E_ / 32), cb>>>(W1 + (size_t)l * E_ * FF,
            pwth + OFF_W1(l), E_, FF);
        gemm_hw_kernel<<<gW1, 256, GEMM_HW_SMEM>>>(phhi, pwth + OFF_W1(l),
            b1 + l * FF, nullptr, pffhi, FF, E_, 1);
        wconvt_h_kernel<<<dim3(E_ / 32, FF / 32), cb>>>(W2 + (size_t)l * FF * E_,
            pwth + OFF_W2(l), FF, E_);
        gemm_h_kernel<<<gW2, 256, GEMM_H_SMEM>>>(pffhi, nullptr, pwth + OFF_W2(l),
            nullptr, nullptr, nullptr, nullptr, ppart, E_, FF, 1024, 1, 0);
        if (l < L_ - 1)
            reduce_ln_kernel<1><<<BT, 256>>>(ppart, 3, b2 + l * E_, px,
                                             ln1g + (l + 1) * E_, ln1b + (l + 1) * E_, phhi, phlo);
        else
            reduce_ln_kernel<0><<<BT, 256>>>(ppart, 3, b2 + l * E_, px,
                                             lnfg, lnfb, phhi, nullptr);
    }
    wconvt_h_kernel<<<dim3(V_ / 32, E_ / 32), cb>>>(Wlm, pwlmh, E_, V_);
    gemm_hw_kernel<<<gVd, 256, GEMM_HW_SMEM>>>(phhi, pwlmh, blm,
                                               logits, nullptr, V_, E_, 0);

    // --- loss ---
    float* loss_dst = nullptr;
    if (out_size == 1)        loss_dst = out;
    else if (out_size > NLOG) loss_dst = out + NLOG;
    if (loss_dst) {
        row_lse_kernel<<<BT, 256>>>(logits, targets, prl);
        loss_reduce_kernel<<<1, 256>>>(prl, loss_dst);
    }
}